// round 10
// baseline (speedup 1.0000x reference)
#include <cuda_runtime.h>

#define VOCAB 1024
#define DIM   64
#define CHUNK 128
#define TPB   128
#define RPT   2   // z rows per thread

// scratch: 0.5 * |codebook_j|^2
__device__ float g_cnorm[VOCAB];

__device__ __forceinline__ unsigned long long pack2(float lo, float hi) {
    unsigned long long u;
    asm("mov.b64 %0, {%1, %2};" : "=l"(u) : "f"(lo), "f"(hi));
    return u;
}
__device__ __forceinline__ void unpack2(unsigned long long u, float& lo, float& hi) {
    asm("mov.b64 {%0, %1}, %2;" : "=f"(lo), "=f"(hi) : "l"(u));
}
__device__ __forceinline__ void ffma2(unsigned long long& acc,
                                      unsigned long long a,
                                      unsigned long long b) {
    // packed fp32x2 FMA — 2x scalar FFMA throughput; only reachable via PTX
    asm("fma.rn.f32x2 %0, %1, %2, %0;" : "+l"(acc) : "l"(a), "l"(b));
}
__device__ __forceinline__ unsigned long long add2(unsigned long long a,
                                                   unsigned long long b) {
    unsigned long long r;
    asm("add.rn.f32x2 %0, %1, %2;" : "=l"(r) : "l"(a), "l"(b));
    return r;
}

__global__ void cnorm_kernel(const float* __restrict__ cb) {
    int j = blockIdx.x * blockDim.x + threadIdx.x;
    if (j < VOCAB) {
        const float4* r = reinterpret_cast<const float4*>(cb + (size_t)j * DIM);
        float s = 0.f;
        #pragma unroll
        for (int i = 0; i < DIM / 4; i++) {
            float4 v = r[i];
            s += v.x * v.x + v.y * v.y + v.z * v.z + v.w * v.w;
        }
        g_cnorm[j] = 0.5f * s;
    }
}

__global__ __launch_bounds__(TPB, 3)
void vq_kernel(const float* __restrict__ z,
               const float* __restrict__ cb,
               float* __restrict__ zq,
               float* __restrict__ tok) {
    // codebook chunk stored as packed f32x2 pairs (16B aligned rows)
    __shared__ ulonglong2 s_cb[CHUNK * DIM / 4];
    __shared__ float s_cn[CHUNK];

    // Two rows per thread, strided by TPB so global loads stay coalesced.
    const int row0 = blockIdx.x * (TPB * RPT) + threadIdx.x;
    const int row1 = row0 + TPB;

    // Hold BOTH z rows in registers, packed as f32x2 (consecutive dim pairs).
    unsigned long long zr0[DIM / 2], zr1[DIM / 2];
    {
        const float4* p0 = reinterpret_cast<const float4*>(z + (size_t)row0 * DIM);
        const float4* p1 = reinterpret_cast<const float4*>(z + (size_t)row1 * DIM);
        #pragma unroll
        for (int i = 0; i < DIM / 4; i++) {
            float4 v = p0[i];
            zr0[2 * i]     = pack2(v.x, v.y);
            zr0[2 * i + 1] = pack2(v.z, v.w);
            float4 w = p1[i];
            zr1[2 * i]     = pack2(w.x, w.y);
            zr1[2 * i + 1] = pack2(w.z, w.w);
        }
    }

    float best0 = 3.402823466e38f, best1 = 3.402823466e38f;
    int bj0 = 0, bj1 = 0;

    for (int base = 0; base < VOCAB; base += CHUNK) {
        __syncthreads();
        {
            const float4* src = reinterpret_cast<const float4*>(cb + (size_t)base * DIM);
            float4* dst = reinterpret_cast<float4*>(s_cb);
            #pragma unroll
            for (int i = threadIdx.x; i < CHUNK * DIM / 4; i += TPB)
                dst[i] = src[i];
            if (threadIdx.x < CHUNK)
                s_cn[threadIdx.x] = g_cnorm[base + threadIdx.x];
        }
        __syncthreads();

        #pragma unroll 1
        for (int jj = 0; jj < CHUNK; jj++) {
            const ulonglong2* crow = s_cb + jj * (DIM / 4);
            const float cn = s_cn[jj];
            // 2 accumulators per row break the FFMA2 RAW chain (lat 4, rt 2)
            unsigned long long a00 = 0ull, a01 = 0ull;
            unsigned long long a10 = 0ull, a11 = 0ull;
            #pragma unroll 4
            for (int i = 0; i < DIM / 4; i++) {
                ulonglong2 c = crow[i];           // broadcast LDS.128 -> two f32x2
                ffma2(a00, zr0[2 * i],     c.x);
                ffma2(a01, zr0[2 * i + 1], c.y);
                ffma2(a10, zr1[2 * i],     c.x);
                ffma2(a11, zr1[2 * i + 1], c.y);
            }
            float l0, h0, l1, h1;
            unpack2(add2(a00, a01), l0, h0);
            unpack2(add2(a10, a11), l1, h1);
            float t0 = cn - (l0 + h0);   // = 0.5|c|^2 - z0.c
            float t1 = cn - (l1 + h1);   // = 0.5|c|^2 - z1.c
            int j = base + jj;
            if (t0 < best0) { best0 = t0; bj0 = j; }  // first-min tiebreak
            if (t1 < best1) { best1 = t1; bj1 = j; }
        }
    }

    // epilogue: tokens (numeric float) + gather z_quantized = codebook[best]
    if (tok) { tok[row0] = (float)bj0; tok[row1] = (float)bj1; }
    {
        const float4* s0 = reinterpret_cast<const float4*>(cb + (size_t)bj0 * DIM);
        float4* d0 = reinterpret_cast<float4*>(zq + (size_t)row0 * DIM);
        const float4* s1 = reinterpret_cast<const float4*>(cb + (size_t)bj1 * DIM);
        float4* d1 = reinterpret_cast<float4*>(zq + (size_t)row1 * DIM);
        #pragma unroll
        for (int i = 0; i < DIM / 4; i++) { d0[i] = s0[i]; d1[i] = s1[i]; }
    }
}

extern "C" void kernel_launch(void* const* d_in, const int* in_sizes, int n_in,
                              void* d_out, int out_size) {
    const float* z  = (const float*)d_in[0];
    const float* cb = (const float*)d_in[1];
    float* out = (float*)d_out;

    const int nrows = in_sizes[0] / DIM;  // 65536

    // Output tuple layout: [z_quantized (nrows*DIM)] [tokens (nrows)] [codebook (VOCAB*DIM)]
    float* zq    = out;
    float* tok   = nullptr;
    float* cbout = nullptr;
    long long pos = (long long)nrows * DIM;
    if ((long long)out_size >= pos + nrows) { tok = out + pos; pos += nrows; }
    if ((long long)out_size >= pos + (long long)VOCAB * DIM) { cbout = out + pos; }

    cnorm_kernel<<<(VOCAB + 255) / 256, 256>>>(cb);
    vq_kernel<<<nrows / (TPB * RPT), TPB>>>(z, cb, zq, tok);
    if (cbout)
        cudaMemcpyAsync(cbout, cb, (size_t)VOCAB * DIM * sizeof(float),
                        cudaMemcpyDeviceToDevice, 0);
}

// round 13
// speedup vs baseline: 3.6992x; 3.6992x over previous
#include <cuda_runtime.h>

#define VOCAB 1024
#define DIM   64
#define CHUNK 128
#define TPB   128
#define RPT   2   // z rows per thread

// scratch: 0.5 * |codebook_j|^2
__device__ float g_cnorm[VOCAB];

__device__ __forceinline__ unsigned long long pack2(float lo, float hi) {
    unsigned long long u;
    asm("mov.b64 %0, {%1, %2};" : "=l"(u) : "f"(lo), "f"(hi));
    return u;
}
__device__ __forceinline__ void unpack2(unsigned long long u, float& lo, float& hi) {
    asm("mov.b64 {%0, %1}, %2;" : "=f"(lo), "=f"(hi) : "l"(u));
}
__device__ __forceinline__ void ffma2(unsigned long long& acc,
                                      unsigned long long a,
                                      unsigned long long b) {
    // packed fp32x2 FMA — 2x scalar FFMA throughput; only reachable via PTX
    asm("fma.rn.f32x2 %0, %1, %2, %0;" : "+l"(acc) : "l"(a), "l"(b));
}
__device__ __forceinline__ unsigned long long add2(unsigned long long a,
                                                   unsigned long long b) {
    unsigned long long r;
    asm("add.rn.f32x2 %0, %1, %2;" : "=l"(r) : "l"(a), "l"(b));
    return r;
}

__global__ void cnorm_kernel(const float* __restrict__ cb) {
    int j = blockIdx.x * blockDim.x + threadIdx.x;
    if (j < VOCAB) {
        const float4* r = reinterpret_cast<const float4*>(cb + (size_t)j * DIM);
        float s = 0.f;
        #pragma unroll
        for (int i = 0; i < DIM / 4; i++) {
            float4 v = r[i];
            s += v.x * v.x + v.y * v.y + v.z * v.z + v.w * v.w;
        }
        g_cnorm[j] = 0.5f * s;
    }
}

__global__ __launch_bounds__(TPB, 2)
void vq_kernel(const float* __restrict__ z,
               const float* __restrict__ cb,
               float* __restrict__ zq,
               float* __restrict__ tok) {
    // codebook chunk stored as packed f32x2 pairs (16B-aligned rows)
    __shared__ ulonglong2 s_cb[CHUNK * DIM / 4];
    __shared__ float s_cn[CHUNK];

    // Two rows per thread, strided by TPB so global loads stay coalesced.
    const int row0 = blockIdx.x * (TPB * RPT) + threadIdx.x;
    const int row1 = row0 + TPB;

    // Hold BOTH z rows in registers, NEGATED, packed as f32x2.
    // Minimizing |c|^2 - 2 z.c  ==  minimizing 0.5|c|^2 + (-z).c
    // NOTE: must stay fully constant-indexed (full unroll) or ptxas demotes
    // these arrays to local memory (R10 regression).
    unsigned long long zr0[DIM / 2], zr1[DIM / 2];
    {
        const float4* p0 = reinterpret_cast<const float4*>(z + (size_t)row0 * DIM);
        const float4* p1 = reinterpret_cast<const float4*>(z + (size_t)row1 * DIM);
        #pragma unroll
        for (int i = 0; i < DIM / 4; i++) {
            float4 v = p0[i];
            zr0[2 * i]     = pack2(-v.x, -v.y);
            zr0[2 * i + 1] = pack2(-v.z, -v.w);
            float4 w = p1[i];
            zr1[2 * i]     = pack2(-w.x, -w.y);
            zr1[2 * i + 1] = pack2(-w.z, -w.w);
        }
    }

    float best0 = 3.402823466e38f, best1 = 3.402823466e38f;
    int bj0 = 0, bj1 = 0;

    for (int base = 0; base < VOCAB; base += CHUNK) {
        __syncthreads();
        {
            const float4* src = reinterpret_cast<const float4*>(cb + (size_t)base * DIM);
            float4* dst = reinterpret_cast<float4*>(s_cb);
            #pragma unroll
            for (int i = threadIdx.x; i < CHUNK * DIM / 4; i += TPB)
                dst[i] = src[i];
            if (threadIdx.x < CHUNK)
                s_cn[threadIdx.x] = g_cnorm[base + threadIdx.x];
        }
        __syncthreads();

        // unroll 2: lets ptxas hoist jj+1's LDS batch under jj's FFMA2 stream
        // and overlap the two serial reduce tails.
        #pragma unroll 2
        for (int jj = 0; jj < CHUNK; jj++) {
            const ulonglong2* crow = s_cb + jj * (DIM / 4);
            // 2 accumulators per row break the FFMA2 RAW chain (lat 4, rt 2);
            // cn folded into acc init so the tail has no extra subtract.
            unsigned long long a00 = pack2(s_cn[jj], 0.f), a01 = 0ull;
            unsigned long long a10 = a00,                  a11 = 0ull;
            #pragma unroll
            for (int i = 0; i < DIM / 4; i++) {
                ulonglong2 c = crow[i];           // broadcast LDS.128 -> two f32x2
                ffma2(a00, zr0[2 * i],     c.x);
                ffma2(a01, zr0[2 * i + 1], c.y);
                ffma2(a10, zr1[2 * i],     c.x);
                ffma2(a11, zr1[2 * i + 1], c.y);
            }
            float l0, h0, l1, h1;
            unpack2(add2(a00, a01), l0, h0);
            unpack2(add2(a10, a11), l1, h1);
            float t0 = l0 + h0;   // = 0.5|c|^2 - z0.c
            float t1 = l1 + h1;   // = 0.5|c|^2 - z1.c
            int j = base + jj;
            if (t0 < best0) { best0 = t0; bj0 = j; }  // first-min tiebreak
            if (t1 < best1) { best1 = t1; bj1 = j; }
        }
    }

    // epilogue: tokens (numeric float) + gather z_quantized = codebook[best]
    if (tok) { tok[row0] = (float)bj0; tok[row1] = (float)bj1; }
    {
        const float4* s0 = reinterpret_cast<const float4*>(cb + (size_t)bj0 * DIM);
        float4* d0 = reinterpret_cast<float4*>(zq + (size_t)row0 * DIM);
        const float4* s1 = reinterpret_cast<const float4*>(cb + (size_t)bj1 * DIM);
        float4* d1 = reinterpret_cast<float4*>(zq + (size_t)row1 * DIM);
        #pragma unroll
        for (int i = 0; i < DIM / 4; i++) { d0[i] = s0[i]; d1[i] = s1[i]; }
    }
}

extern "C" void kernel_launch(void* const* d_in, const int* in_sizes, int n_in,
                              void* d_out, int out_size) {
    const float* z  = (const float*)d_in[0];
    const float* cb = (const float*)d_in[1];
    float* out = (float*)d_out;

    const int nrows = in_sizes[0] / DIM;  // 65536

    // Output tuple layout: [z_quantized (nrows*DIM)] [tokens (nrows)] [codebook (VOCAB*DIM)]
    float* zq    = out;
    float* tok   = nullptr;
    float* cbout = nullptr;
    long long pos = (long long)nrows * DIM;
    if ((long long)out_size >= pos + nrows) { tok = out + pos; pos += nrows; }
    if ((long long)out_size >= pos + (long long)VOCAB * DIM) { cbout = out + pos; }

    cnorm_kernel<<<(VOCAB + 255) / 256, 256>>>(cb);
    vq_kernel<<<nrows / (TPB * RPT), TPB>>>(z, cb, zq, tok);
    if (cbout)
        cudaMemcpyAsync(cbout, cb, (size_t)VOCAB * DIM * sizeof(float),
                        cudaMemcpyDeviceToDevice, 0);
}